// round 6
// baseline (speedup 1.0000x reference)
#include <cuda_runtime.h>
#include <math.h>

// x (8,64,256,256) fp32, conv_w (64,64,3), conv_b (64) -> out (8,64,256,256) fp32
// out_o = z0 + z1 M1^T + z2 M2^T
//       + (M1 (z1 a0)) a7^T + (M1 (z2 a0)) a6^T + (M1 (z2 a1)) a7^T + b_o g g^T
// z[px][j=o*3+kk] = sum_ch X[px][ch] W[j][ch], via mma.sync tf32 m16n8k8.
// R6: 512 threads/CTA (16 warps) for latency hiding; same smem layout as R5.

typedef unsigned int u32;

__device__ float c_all[160];  // [0:64) M1, [64:128) M2, [128:136) a1, [136:144) a6, [144:152) a7, [152:160) g

__device__ double Dkn(int k, int n) {
    const double PI = 3.14159265358979323846;
    double v = 0.5 * cos(PI * (2.0 * n + 1.0) * (double)k / 16.0);
    if (k == 0) v *= 0.7071067811865476;
    return v;
}

__global__ void init_consts_kernel() {
    int t = threadIdx.x;
    if (t >= 160) return;
    double r = 0.0;
    if (t < 64) {
        int p = t >> 3, q = t & 7;
        for (int n = 0; n < 7; n++) r += Dkn(n, p) * Dkn(n + 1, q);
    } else if (t < 128) {
        int s = t - 64; int p = s >> 3, q = s & 7;
        for (int n = 0; n < 6; n++) r += Dkn(n, p) * Dkn(n + 2, q);
    } else if (t < 136) r = Dkn(1, t - 128);
    else if (t < 144)   r = Dkn(6, t - 136);
    else if (t < 152)   r = Dkn(7, t - 144);
    else {
        int n = t - 152;
        for (int k = 0; k < 8; k++) r += Dkn(k, n);
    }
    c_all[t] = (float)r;
}

// smem float offsets
#define XS_F 0                       // Xs2[64 ch][264] (px 0..255), stride 264 (== 8 mod 32)
#define WT_F (64 * 264)              // Wt[64 ch][200]  (j 0..191),  stride 200 (== 8 mod 32)
#define ZB_F (WT_F + 64 * 200)       // Zb[48 jl][268]  (px 0..255), stride 268
#define TS_F (ZB_F + 48 * 268)       // Ts[64 ub][24]
#define SC_F (TS_F + 64 * 24)        // consts [160]
#define SM_FLOATS (SC_F + 160)       // 44,256 floats = 177,024 B -> 1 CTA/SM

__device__ __forceinline__ float tf32r(float f) {
    u32 r;
    asm("cvt.rna.tf32.f32 %0, %1;" : "=r"(r) : "f"(f));
    return __uint_as_float(r);
}

__device__ __forceinline__ void mma_tf32(float* d, const float* a, const float* b) {
    asm volatile(
        "mma.sync.aligned.m16n8k8.row.col.f32.tf32.tf32.f32 "
        "{%0,%1,%2,%3}, {%4,%5,%6,%7}, {%8,%9}, {%0,%1,%2,%3};"
        : "+f"(d[0]), "+f"(d[1]), "+f"(d[2]), "+f"(d[3])
        : "r"(__float_as_uint(a[0])), "r"(__float_as_uint(a[1])),
          "r"(__float_as_uint(a[2])), "r"(__float_as_uint(a[3])),
          "r"(__float_as_uint(b[0])), "r"(__float_as_uint(b[1])));
}

__device__ __forceinline__ float dot4(float4 a, float4 b) {
    return a.x * b.x + a.y * b.y + a.z * b.z + a.w * b.w;
}

__global__ void __launch_bounds__(512) dctconv_mma(
    const float* __restrict__ x,
    const float* __restrict__ cw,
    const float* __restrict__ cb,
    float* __restrict__ out)
{
    extern __shared__ float sm[];
    float* Xs2 = sm + XS_F;
    float* Wt  = sm + WT_F;
    float* Zb  = sm + ZB_F;
    float* Ts  = sm + TS_F;
    float* sC  = sm + SC_F;

    const int tid = threadIdx.x;
    const int wid = tid >> 5;
    const int lane = tid & 31;
    const int g = lane >> 2;     // 0..7
    const int c = lane & 3;      // 0..3
    const int y0 = blockIdx.y * 8;
    const int x0 = blockIdx.x * 32;
    const size_t bb = blockIdx.z;

    if (tid < 160) sC[tid] = c_all[tid];

    // ---- stage X: Xs2[ch][px], px = B*64 + r*8 + cc (block-major), tf32-rounded ----
    const float* xb = x + bb * (size_t)(64 * 65536);
    #pragma unroll
    for (int k = 0; k < 8; k++) {
        int v = tid + 512 * k;
        int i = v >> 6, q = v & 63;
        int r = q >> 3, h = q & 7;
        float4 t = *(const float4*)(xb + (size_t)i * 65536 + (y0 + r) * 256 + x0 + h * 4);
        t.x = tf32r(t.x); t.y = tf32r(t.y); t.z = tf32r(t.z); t.w = tf32r(t.w);
        int pxb = (h >> 1) * 64 + r * 8 + 4 * (h & 1);
        *(float4*)(Xs2 + i * 264 + pxb) = t;
    }
    // ---- stage W: Wt[ch][j = o*3+kk], tf32-rounded ----
    for (int v = tid; v < 12288; v += 512) {
        int o = v / 192, rem = v - o * 192;
        int i = rem / 3, kk = rem - i * 3;
        Wt[i * 200 + o * 3 + kk] = tf32r(cw[v]);
    }
    __syncthreads();

    const float* sM1 = sC;
    const float* sM2 = sC + 64;
    const float* sA1 = sC + 128;
    const float* sA6 = sC + 136;
    const float* sA7 = sC + 144;
    const float* sG  = sC + 152;

    // 16 warps: 8 m-groups (32 px each) x 2 n-groups (24 j each)
    const int mg = wid >> 1;         // 0..7
    const int ng = wid & 1;          // 0..1
    const int px0 = mg * 32;
    const int jb = ng * 24;

    for (int oc = 0; oc < 4; oc++) {
        // ---- GEMM: Z[px][j] for j in [oc*48, oc*48+48) ----
        {
            float acc[2][3][4];
            #pragma unroll
            for (int t = 0; t < 2; t++)
                #pragma unroll
                for (int nt = 0; nt < 3; nt++)
                    #pragma unroll
                    for (int e = 0; e < 4; e++) acc[t][nt][e] = 0.f;

            #pragma unroll 2
            for (int k8 = 0; k8 < 8; k8++) {
                const int k0 = k8 * 8;
                const float* Xc0 = Xs2 + (k0 + c) * 264 + px0 + g;
                const float* Xc4 = Xc0 + 4 * 264;
                float a[2][4];
                #pragma unroll
                for (int t = 0; t < 2; t++) {
                    a[t][0] = Xc0[16 * t];
                    a[t][1] = Xc0[16 * t + 8];
                    a[t][2] = Xc4[16 * t];
                    a[t][3] = Xc4[16 * t + 8];
                }
                const float* Wc0 = Wt + (k0 + c) * 200 + oc * 48 + jb + g;
                const float* Wc4 = Wc0 + 4 * 200;
                float b[3][2];
                #pragma unroll
                for (int nt = 0; nt < 3; nt++) {
                    b[nt][0] = Wc0[8 * nt];
                    b[nt][1] = Wc4[8 * nt];
                }
                #pragma unroll
                for (int t = 0; t < 2; t++)
                    #pragma unroll
                    for (int nt = 0; nt < 3; nt++)
                        mma_tf32(acc[t][nt], a[t], b[nt]);
            }
            // D-frag store: d0=(g,2c), d1=(g,2c+1), d2=(g+8,2c), d3=(g+8,2c+1)
            #pragma unroll
            for (int t = 0; t < 2; t++)
                #pragma unroll
                for (int nt = 0; nt < 3; nt++) {
                    int jl = jb + nt * 8 + 2 * c;
                    int pxb = px0 + 16 * t + g;
                    Zb[jl * 268 + pxb]           = acc[t][nt][0];
                    Zb[(jl + 1) * 268 + pxb]     = acc[t][nt][1];
                    Zb[jl * 268 + pxb + 8]       = acc[t][nt][2];
                    Zb[(jl + 1) * 268 + pxb + 8] = acc[t][nt][3];
                }
        }
        __syncthreads();

        // ---- Tsum: per (u,B): which0 = row-sums z1, which1 = row-sums z2, which2 = dot(z2, a1) ----
        {
            float4 a1a = *(const float4*)sA1;
            float4 a1b = *(const float4*)(sA1 + 4);
            #pragma unroll
            for (int vv = 0; vv < 3; vv++) {
                int v = tid + 512 * vv;          // 1536 values
                int s = v & 7;
                int t2 = v >> 3;
                int which = t2 % 3;
                int ub = t2 / 3;                 // u*4 + B
                int jrow = (ub >> 2) * 3 + ((which == 0) ? 1 : 2);
                const float* zr = Zb + jrow * 268 + (ub & 3) * 64 + s * 8;
                float4 za = *(const float4*)zr;
                float4 zc = *(const float4*)(zr + 4);
                float acc;
                if (which == 2)
                    acc = dot4(za, a1a) + dot4(zc, a1b);
                else
                    acc = za.x + za.y + za.z + za.w + zc.x + zc.y + zc.z + zc.w;
                Ts[ub * 24 + which * 8 + s] = acc;
            }
        }
        __syncthreads();

        // ---- Phase B: spatial epilogue, 1 unit per thread: (u, B, r) ----
        {
            int u = tid >> 5;
            int B = (tid >> 3) & 3;
            int r = tid & 7;
            const float* z0p = Zb + (u * 3) * 268 + B * 64 + r * 8;
            float4 z0a = *(const float4*)z0p,          z0b = *(const float4*)(z0p + 4);
            float4 z1a = *(const float4*)(z0p + 268),  z1b = *(const float4*)(z0p + 272);
            float4 z2a = *(const float4*)(z0p + 536),  z2b = *(const float4*)(z0p + 540);
            const float* ts = Ts + (u * 4 + B) * 24;
            float4 t0a = *(const float4*)ts,        t0b = *(const float4*)(ts + 4);
            float4 t1a = *(const float4*)(ts + 8),  t1b = *(const float4*)(ts + 12);
            float4 t2a = *(const float4*)(ts + 16), t2b = *(const float4*)(ts + 20);
            float4 m1ra = *(const float4*)(sM1 + r * 8);
            float4 m1rb = *(const float4*)(sM1 + r * 8 + 4);

            float w1 = dot4(m1ra, t0a) + dot4(m1rb, t0b);
            float w2 = dot4(m1ra, t1a) + dot4(m1rb, t1b);
            float w3 = dot4(m1ra, t2a) + dot4(m1rb, t2b);

            const int o = oc * 16 + u;
            const float bias = __ldg(cb + o);
            const float inv_s8 = 0.3535533905932738f;  // 1/sqrt(8)
            const float wa7 = w1 * inv_s8 + w3;
            const float wa6 = w2 * inv_s8;
            const float gb  = bias * sG[r];

            float a[8];
            #pragma unroll
            for (int cc = 0; cc < 8; cc++) {
                float4 m1a = *(const float4*)(sM1 + cc * 8);
                float4 m1b = *(const float4*)(sM1 + cc * 8 + 4);
                float4 m2a = *(const float4*)(sM2 + cc * 8);
                float4 m2b = *(const float4*)(sM2 + cc * 8 + 4);
                float v = (cc < 4 ? ((const float*)&z0a)[cc] : ((const float*)&z0b)[cc - 4]);
                v += dot4(m1a, z1a) + dot4(m1b, z1b);
                v += dot4(m2a, z2a) + dot4(m2b, z2b);
                v += wa7 * sA7[cc] + wa6 * sA6[cc] + gb * sG[cc];
                a[cc] = v;
            }

            float* outp = out + (bb * 64 + o) * (size_t)65536
                              + (size_t)(y0 + r) * 256 + x0 + B * 8;
            *(float4*)outp       = make_float4(a[0], a[1], a[2], a[3]);
            *(float4*)(outp + 4) = make_float4(a[4], a[5], a[6], a[7]);
        }
        __syncthreads();
    }
}

extern "C" void kernel_launch(void* const* d_in, const int* in_sizes, int n_in,
                              void* d_out, int out_size) {
    const float* x  = (const float*)d_in[0];
    const float* cw = (const float*)d_in[1];
    const float* cb = (const float*)d_in[2];
    float* out = (float*)d_out;
    (void)in_sizes; (void)n_in; (void)out_size;

    cudaFuncSetAttribute(dctconv_mma, cudaFuncAttributeMaxDynamicSharedMemorySize,
                         SM_FLOATS * (int)sizeof(float));

    init_consts_kernel<<<1, 192>>>();
    dim3 grid(8, 32, 8);   // (W/32, H/8, bsz)
    dctconv_mma<<<grid, 512, SM_FLOATS * sizeof(float)>>>(x, cw, cb, out);
}

// round 7
// speedup vs baseline: 1.0870x; 1.0870x over previous
#include <cuda_runtime.h>
#include <math.h>

// x (8,64,256,256) fp32, conv_w (64,64,3), conv_b (64) -> out (8,64,256,256) fp32
// out_o = z0 + z1 M1^T + z2 M2^T
//       + (M1 (z1 a0)) a7^T + (M1 (z2 a0)) a6^T + (M1 (z2 a1)) a7^T + b_o g g^T
// z[px][j=o*3+kk] = sum_ch X[px][ch] W[j][ch], via mma.sync tf32 m16n8k8.
// R7: fused Tsum via shuffles, swizzled double-buffered Zb, 1 barrier per oc.

typedef unsigned int u32;

__device__ float c_all[160];  // [0:64) M1, [64:128) M2, [128:136) a1, [136:144) a6, [144:152) a7, [152:160) g

__device__ double Dkn(int k, int n) {
    const double PI = 3.14159265358979323846;
    double v = 0.5 * cos(PI * (2.0 * n + 1.0) * (double)k / 16.0);
    if (k == 0) v *= 0.7071067811865476;
    return v;
}

__global__ void init_consts_kernel() {
    int t = threadIdx.x;
    if (t >= 160) return;
    double r = 0.0;
    if (t < 64) {
        int p = t >> 3, q = t & 7;
        for (int n = 0; n < 7; n++) r += Dkn(n, p) * Dkn(n + 1, q);
    } else if (t < 128) {
        int s = t - 64; int p = s >> 3, q = s & 7;
        for (int n = 0; n < 6; n++) r += Dkn(n, p) * Dkn(n + 2, q);
    } else if (t < 136) r = Dkn(1, t - 128);
    else if (t < 144)   r = Dkn(6, t - 136);
    else if (t < 152)   r = Dkn(7, t - 144);
    else {
        int n = t - 152;
        for (int k = 0; k < 8; k++) r += Dkn(k, n);
    }
    c_all[t] = (float)r;
}

// smem float offsets
#define XS_F 0                 // Xs2[64 ch][264] (px 0..255), stride 264 (== 8 mod 32)
#define WT_F 16896             // Wt[64 ch][200]  (j 0..191),  stride 200 (== 8 mod 32)
#define ZB0_F 29696            // Zb0[48 jl][268] swizzled px
#define ZB1_F 42560            // Zb1[48 jl][268]
#define SC_F 55424             // consts [160]
#define SM_FLOATS 55584        // 222,336 B (opt-in max smem)

__device__ __forceinline__ float tf32r(float f) {
    u32 r;
    asm("cvt.rna.tf32.f32 %0, %1;" : "=r"(r) : "f"(f));
    return __uint_as_float(r);
}

__device__ __forceinline__ void mma_tf32(float* d, const float* a, const float* b) {
    asm volatile(
        "mma.sync.aligned.m16n8k8.row.col.f32.tf32.tf32.f32 "
        "{%0,%1,%2,%3}, {%4,%5,%6,%7}, {%8,%9}, {%0,%1,%2,%3};"
        : "+f"(d[0]), "+f"(d[1]), "+f"(d[2]), "+f"(d[3])
        : "r"(__float_as_uint(a[0])), "r"(__float_as_uint(a[1])),
          "r"(__float_as_uint(a[2])), "r"(__float_as_uint(a[3])),
          "r"(__float_as_uint(b[0])), "r"(__float_as_uint(b[1])));
}

__device__ __forceinline__ float dot4(float4 a, float4 b) {
    return a.x * b.x + a.y * b.y + a.z * b.z + a.w * b.w;
}
__device__ __forceinline__ float hsum4(float4 a) { return a.x + a.y + a.z + a.w; }

__global__ void __launch_bounds__(512) dctconv_mma(
    const float* __restrict__ x,
    const float* __restrict__ cw,
    const float* __restrict__ cb,
    float* __restrict__ out)
{
    extern __shared__ float sm[];
    float* Xs2 = sm + XS_F;
    float* Wt  = sm + WT_F;
    float* sC  = sm + SC_F;

    const int tid = threadIdx.x;
    const int wid = tid >> 5;
    const int lane = tid & 31;
    const int g = lane >> 2;     // 0..7
    const int c = lane & 3;      // 0..3
    const int y0 = blockIdx.y * 8;
    const int x0 = blockIdx.x * 32;
    const size_t bb = blockIdx.z;

    if (tid < 160) sC[tid] = c_all[tid];

    // ---- stage X: Xs2[ch][px], px = B*64 + r*8 + cc (block-major), tf32-rounded ----
    const float* xb = x + bb * (size_t)(64 * 65536);
    #pragma unroll
    for (int k = 0; k < 8; k++) {
        int v = tid + 512 * k;
        int i = v >> 6, q = v & 63;
        int r = q >> 3, h = q & 7;
        float4 t = *(const float4*)(xb + (size_t)i * 65536 + (y0 + r) * 256 + x0 + h * 4);
        t.x = tf32r(t.x); t.y = tf32r(t.y); t.z = tf32r(t.z); t.w = tf32r(t.w);
        int pxb = (h >> 1) * 64 + r * 8 + 4 * (h & 1);
        *(float4*)(Xs2 + i * 264 + pxb) = t;
    }
    // ---- stage W: Wt[ch][j = o*3+kk], tf32-rounded ----
    for (int v = tid; v < 12288; v += 512) {
        int o = v / 192, rem = v - o * 192;
        int i = rem / 3, kk = rem - i * 3;
        Wt[i * 200 + o * 3 + kk] = tf32r(cw[v]);
    }
    __syncthreads();

    const float* sM1 = sC;
    const float* sM2 = sC + 64;
    const float* sA1 = sC + 128;
    const float* sA6 = sC + 136;
    const float* sA7 = sC + 144;
    const float* sG  = sC + 152;

    // GEMM mapping: 16 warps = 8 m-groups (32 px) x 2 n-groups (24 j)
    const int mg = wid >> 1;
    const int ng = wid & 1;
    const int px0 = mg * 32;
    const int jb = ng * 24;
    const u32 sxor = (mg & 1) << 2;     // Zb px swizzle shift for this warp's stores

    // GEMM for oc-group k: Z[px][j], j in [k*48, k*48+48), into buffer Zw
    auto gemm_store = [&](int k, float* Zw) {
        float acc[2][3][4];
        #pragma unroll
        for (int t = 0; t < 2; t++)
            #pragma unroll
            for (int nt = 0; nt < 3; nt++)
                #pragma unroll
                for (int e = 0; e < 4; e++) acc[t][nt][e] = 0.f;

        #pragma unroll 2
        for (int k8 = 0; k8 < 8; k8++) {
            const int k0 = k8 * 8;
            const float* Xc0 = Xs2 + (k0 + c) * 264 + px0 + g;
            const float* Xc4 = Xc0 + 4 * 264;
            float a[2][4];
            #pragma unroll
            for (int t = 0; t < 2; t++) {
                a[t][0] = Xc0[16 * t];
                a[t][1] = Xc0[16 * t + 8];
                a[t][2] = Xc4[16 * t];
                a[t][3] = Xc4[16 * t + 8];
            }
            const float* Wc0 = Wt + (k0 + c) * 200 + k * 48 + jb + g;
            const float* Wc4 = Wc0 + 4 * 200;
            float b[3][2];
            #pragma unroll
            for (int nt = 0; nt < 3; nt++) {
                b[nt][0] = Wc0[8 * nt];
                b[nt][1] = Wc4[8 * nt];
            }
            #pragma unroll
            for (int t = 0; t < 2; t++)
                #pragma unroll
                for (int nt = 0; nt < 3; nt++)
                    mma_tf32(acc[t][nt], a[t], b[nt]);
        }
        // D-frag store with px swizzle (px ^= ((px>>5)&1)<<2 == sxor, warp-uniform)
        #pragma unroll
        for (int t = 0; t < 2; t++)
            #pragma unroll
            for (int nt = 0; nt < 3; nt++) {
                int jl = jb + nt * 8 + 2 * c;
                int pxs = (px0 + 16 * t + g) ^ sxor;
                Zw[jl * 268 + pxs]           = acc[t][nt][0];
                Zw[(jl + 1) * 268 + pxs]     = acc[t][nt][1];
                Zw[jl * 268 + (pxs ^ 8)]     = acc[t][nt][2];   // +8 keeps bit5, swizzle commutes
                Zw[(jl + 1) * 268 + (pxs ^ 8)] = acc[t][nt][3];
            }
    };

    // epilogue unit mapping: u = wid, B = (lane>>3), r = lane&7
    const int ue = wid;
    const int Be = lane >> 3;
    const int re = lane & 7;
    const int s4 = (re & 4) << 0 ? ((re & 4) ? 4 : 0) : 0;  // 4 if r>=4 else 0
    const int ro = re * 8;

    auto epilogue = [&](int oc, const float* Zr) {
        const float* zp = Zr + (ue * 3) * 268 + Be * 64;
        const int o0 = ro + ((re & 4) ? 4 : 0);
        const int o1 = ro + ((re & 4) ? 0 : 4);
        float4 z0a = *(const float4*)(zp + o0),        z0b = *(const float4*)(zp + o1);
        float4 z1a = *(const float4*)(zp + 268 + o0),  z1b = *(const float4*)(zp + 268 + o1);
        float4 z2a = *(const float4*)(zp + 536 + o0),  z2b = *(const float4*)(zp + 536 + o1);

        // per-row stats (this thread's row re is row s=re for the shuffle exchange)
        float4 a1a = *(const float4*)sA1;
        float4 a1b = *(const float4*)(sA1 + 4);
        float ts0 = hsum4(z1a) + hsum4(z1b);
        float ts1 = hsum4(z2a) + hsum4(z2b);
        float ts2 = dot4(z2a, a1a) + dot4(z2b, a1b);

        float4 m1ra = *(const float4*)(sM1 + re * 8);
        float4 m1rb = *(const float4*)(sM1 + re * 8 + 4);
        float m1rv[8] = {m1ra.x, m1ra.y, m1ra.z, m1ra.w, m1rb.x, m1rb.y, m1rb.z, m1rb.w};

        float w1 = 0.f, w2 = 0.f, w3 = 0.f;
        const int lbase = lane & 24;
        #pragma unroll
        for (int s = 0; s < 8; s++) {
            float t0 = __shfl_sync(0xffffffffu, ts0, lbase + s);
            float t1 = __shfl_sync(0xffffffffu, ts1, lbase + s);
            float t2 = __shfl_sync(0xffffffffu, ts2, lbase + s);
            w1 += m1rv[s] * t0;
            w2 += m1rv[s] * t1;
            w3 += m1rv[s] * t2;
        }

        const int o = oc * 16 + ue;
        const float bias = __ldg(cb + o);
        const float inv_s8 = 0.3535533905932738f;  // 1/sqrt(8)
        const float wa7 = w1 * inv_s8 + w3;
        const float wa6 = w2 * inv_s8;
        const float gb  = bias * sG[re];

        float a[8];
        #pragma unroll
        for (int cc = 0; cc < 8; cc++) {
            float4 m1a = *(const float4*)(sM1 + cc * 8);
            float4 m1b = *(const float4*)(sM1 + cc * 8 + 4);
            float4 m2a = *(const float4*)(sM2 + cc * 8);
            float4 m2b = *(const float4*)(sM2 + cc * 8 + 4);
            float v = (cc < 4 ? ((const float*)&z0a)[cc] : ((const float*)&z0b)[cc - 4]);
            v += dot4(m1a, z1a) + dot4(m1b, z1b);
            v += dot4(m2a, z2a) + dot4(m2b, z2b);
            v += wa7 * sA7[cc] + wa6 * sA6[cc] + gb * sG[cc];
            a[cc] = v;
        }

        float* outp = out + (bb * 64 + o) * (size_t)65536
                          + (size_t)(y0 + re) * 256 + x0 + Be * 8;
        *(float4*)outp       = make_float4(a[0], a[1], a[2], a[3]);
        *(float4*)(outp + 4) = make_float4(a[4], a[5], a[6], a[7]);
    };
    (void)s4;

    // ---- software pipeline: 1 barrier per oc ----
    gemm_store(0, sm + ZB0_F);
    __syncthreads();
    #pragma unroll
    for (int oc = 0; oc < 4; oc++) {
        if (oc < 3) gemm_store(oc + 1, sm + ((oc & 1) ? ZB0_F : ZB1_F));
        epilogue(oc, sm + ((oc & 1) ? ZB1_F : ZB0_F));
        __syncthreads();
    }
}

extern "C" void kernel_launch(void* const* d_in, const int* in_sizes, int n_in,
                              void* d_out, int out_size) {
    const float* x  = (const float*)d_in[0];
    const float* cw = (const float*)d_in[1];
    const float* cb = (const float*)d_in[2];
    float* out = (float*)d_out;
    (void)in_sizes; (void)n_in; (void)out_size;

    cudaFuncSetAttribute(dctconv_mma, cudaFuncAttributeMaxDynamicSharedMemorySize,
                         SM_FLOATS * (int)sizeof(float));

    init_consts_kernel<<<1, 192>>>();
    dim3 grid(8, 32, 8);   // (W/32, H/8, bsz)
    dctconv_mma<<<grid, 512, SM_FLOATS * sizeof(float)>>>(x, cw, cb, out);
}

// round 8
// speedup vs baseline: 1.1366x; 1.0456x over previous
#include <cuda_runtime.h>
#include <math.h>

// x (8,64,256,256) fp32, conv_w (64,64,3), conv_b (64) -> out (8,64,256,256) fp32
// out_o = z0 + z1 M1^T + z2 M2^T
//       + (M1 (z1 a0)) a7^T + (M1 (z2 a0)) a6^T + (M1 (z2 a1)) a7^T + b_o g g^T
// z[px][j=o*3+kk] = sum_ch X[px][ch] W[j][ch], via mma.sync tf32 m16n8k8.
// R8: X (a) fragments hoisted into registers across the oc loop (oc-invariant).

typedef unsigned int u32;

__device__ float c_all[160];  // [0:64) M1, [64:128) M2, [128:136) a1, [136:144) a6, [144:152) a7, [152:160) g

__device__ double Dkn(int k, int n) {
    const double PI = 3.14159265358979323846;
    double v = 0.5 * cos(PI * (2.0 * n + 1.0) * (double)k / 16.0);
    if (k == 0) v *= 0.7071067811865476;
    return v;
}

__global__ void init_consts_kernel() {
    int t = threadIdx.x;
    if (t >= 160) return;
    double r = 0.0;
    if (t < 64) {
        int p = t >> 3, q = t & 7;
        for (int n = 0; n < 7; n++) r += Dkn(n, p) * Dkn(n + 1, q);
    } else if (t < 128) {
        int s = t - 64; int p = s >> 3, q = s & 7;
        for (int n = 0; n < 6; n++) r += Dkn(n, p) * Dkn(n + 2, q);
    } else if (t < 136) r = Dkn(1, t - 128);
    else if (t < 144)   r = Dkn(6, t - 136);
    else if (t < 152)   r = Dkn(7, t - 144);
    else {
        int n = t - 152;
        for (int k = 0; k < 8; k++) r += Dkn(k, n);
    }
    c_all[t] = (float)r;
}

// smem float offsets
#define XS_F 0                 // Xs2[64 ch][264] (px 0..255), stride 264 (== 8 mod 32)
#define WT_F 16896             // Wt[64 ch][200]  (j 0..191),  stride 200 (== 8 mod 32)
#define ZB0_F 29696            // Zb0[48 jl][268] swizzled px
#define ZB1_F 42560            // Zb1[48 jl][268]
#define SC_F 55424             // consts [160]
#define SM_FLOATS 55584        // 222,336 B

__device__ __forceinline__ float tf32r(float f) {
    u32 r;
    asm("cvt.rna.tf32.f32 %0, %1;" : "=r"(r) : "f"(f));
    return __uint_as_float(r);
}

__device__ __forceinline__ void mma_tf32(float* d, const float* a, const float* b) {
    asm volatile(
        "mma.sync.aligned.m16n8k8.row.col.f32.tf32.tf32.f32 "
        "{%0,%1,%2,%3}, {%4,%5,%6,%7}, {%8,%9}, {%0,%1,%2,%3};"
        : "+f"(d[0]), "+f"(d[1]), "+f"(d[2]), "+f"(d[3])
        : "r"(__float_as_uint(a[0])), "r"(__float_as_uint(a[1])),
          "r"(__float_as_uint(a[2])), "r"(__float_as_uint(a[3])),
          "r"(__float_as_uint(b[0])), "r"(__float_as_uint(b[1])));
}

__device__ __forceinline__ float dot4(float4 a, float4 b) {
    return a.x * b.x + a.y * b.y + a.z * b.z + a.w * b.w;
}
__device__ __forceinline__ float hsum4(float4 a) { return a.x + a.y + a.z + a.w; }

__global__ void __launch_bounds__(512) dctconv_mma(
    const float* __restrict__ x,
    const float* __restrict__ cw,
    const float* __restrict__ cb,
    float* __restrict__ out)
{
    extern __shared__ float sm[];
    float* Xs2 = sm + XS_F;
    float* Wt  = sm + WT_F;
    float* sC  = sm + SC_F;

    const int tid = threadIdx.x;
    const int wid = tid >> 5;
    const int lane = tid & 31;
    const int g = lane >> 2;     // 0..7
    const int c = lane & 3;      // 0..3
    const int y0 = blockIdx.y * 8;
    const int x0 = blockIdx.x * 32;
    const size_t bb = blockIdx.z;

    if (tid < 160) sC[tid] = c_all[tid];

    // ---- stage X: Xs2[ch][px], px = B*64 + r*8 + cc (block-major), tf32-rounded ----
    const float* xb = x + bb * (size_t)(64 * 65536);
    #pragma unroll
    for (int k = 0; k < 8; k++) {
        int v = tid + 512 * k;
        int i = v >> 6, q = v & 63;
        int r = q >> 3, h = q & 7;
        float4 t = *(const float4*)(xb + (size_t)i * 65536 + (y0 + r) * 256 + x0 + h * 4);
        t.x = tf32r(t.x); t.y = tf32r(t.y); t.z = tf32r(t.z); t.w = tf32r(t.w);
        int pxb = (h >> 1) * 64 + r * 8 + 4 * (h & 1);
        *(float4*)(Xs2 + i * 264 + pxb) = t;
    }
    // ---- stage W: Wt[ch][j = o*3+kk], tf32-rounded ----
    for (int v = tid; v < 12288; v += 512) {
        int o = v / 192, rem = v - o * 192;
        int i = rem / 3, kk = rem - i * 3;
        Wt[i * 200 + o * 3 + kk] = tf32r(cw[v]);
    }
    __syncthreads();

    const float* sM1 = sC;
    const float* sM2 = sC + 64;
    const float* sA1 = sC + 128;
    const float* sA6 = sC + 136;
    const float* sA7 = sC + 144;
    const float* sG  = sC + 152;

    // GEMM mapping: 16 warps = 8 m-groups (32 px) x 2 n-groups (24 j)
    const int mg = wid >> 1;
    const int ng = wid & 1;
    const int px0 = mg * 32;
    const int jb = ng * 24;
    const u32 sxor = (mg & 1) << 2;     // Zb px swizzle shift for this warp's stores

    // ---- hoist oc-invariant a-fragments: af[k8][t][4], 64 regs ----
    float af[8][2][4];
    #pragma unroll
    for (int k8 = 0; k8 < 8; k8++) {
        const float* Xc0 = Xs2 + (k8 * 8 + c) * 264 + px0 + g;
        const float* Xc4 = Xc0 + 4 * 264;
        #pragma unroll
        for (int t = 0; t < 2; t++) {
            af[k8][t][0] = Xc0[16 * t];
            af[k8][t][1] = Xc0[16 * t + 8];
            af[k8][t][2] = Xc4[16 * t];
            af[k8][t][3] = Xc4[16 * t + 8];
        }
    }

    // GEMM for oc-group k: Z[px][j], j in [k*48, k*48+48), into buffer Zw
    auto gemm_store = [&](int k, float* Zw) {
        float acc[2][3][4];
        #pragma unroll
        for (int t = 0; t < 2; t++)
            #pragma unroll
            for (int nt = 0; nt < 3; nt++)
                #pragma unroll
                for (int e = 0; e < 4; e++) acc[t][nt][e] = 0.f;

        #pragma unroll
        for (int k8 = 0; k8 < 8; k8++) {
            const float* Wc0 = Wt + (k8 * 8 + c) * 200 + k * 48 + jb + g;
            const float* Wc4 = Wc0 + 4 * 200;
            float b[3][2];
            #pragma unroll
            for (int nt = 0; nt < 3; nt++) {
                b[nt][0] = Wc0[8 * nt];
                b[nt][1] = Wc4[8 * nt];
            }
            #pragma unroll
            for (int t = 0; t < 2; t++)
                #pragma unroll
                for (int nt = 0; nt < 3; nt++)
                    mma_tf32(acc[t][nt], af[k8][t], b[nt]);
        }
        // D-frag store with px swizzle (warp-uniform sxor)
        #pragma unroll
        for (int t = 0; t < 2; t++)
            #pragma unroll
            for (int nt = 0; nt < 3; nt++) {
                int jl = jb + nt * 8 + 2 * c;
                int pxs = (px0 + 16 * t + g) ^ sxor;
                Zw[jl * 268 + pxs]             = acc[t][nt][0];
                Zw[(jl + 1) * 268 + pxs]       = acc[t][nt][1];
                Zw[jl * 268 + (pxs ^ 8)]       = acc[t][nt][2];
                Zw[(jl + 1) * 268 + (pxs ^ 8)] = acc[t][nt][3];
            }
    };

    // epilogue unit mapping: u = wid, B = (lane>>3), r = lane&7
    const int ue = wid;
    const int Be = lane >> 3;
    const int re = lane & 7;
    const int ro = re * 8;

    auto epilogue = [&](int oc, const float* Zr) {
        const float* zp = Zr + (ue * 3) * 268 + Be * 64;
        const int o0 = ro + ((re & 4) ? 4 : 0);
        const int o1 = ro + ((re & 4) ? 0 : 4);
        float4 z0a = *(const float4*)(zp + o0),        z0b = *(const float4*)(zp + o1);
        float4 z1a = *(const float4*)(zp + 268 + o0),  z1b = *(const float4*)(zp + 268 + o1);
        float4 z2a = *(const float4*)(zp + 536 + o0),  z2b = *(const float4*)(zp + 536 + o1);

        float4 a1a = *(const float4*)sA1;
        float4 a1b = *(const float4*)(sA1 + 4);
        float ts0 = hsum4(z1a) + hsum4(z1b);
        float ts1 = hsum4(z2a) + hsum4(z2b);
        float ts2 = dot4(z2a, a1a) + dot4(z2b, a1b);

        float4 m1ra = *(const float4*)(sM1 + re * 8);
        float4 m1rb = *(const float4*)(sM1 + re * 8 + 4);
        float m1rv[8] = {m1ra.x, m1ra.y, m1ra.z, m1ra.w, m1rb.x, m1rb.y, m1rb.z, m1rb.w};

        float w1 = 0.f, w2 = 0.f, w3 = 0.f;
        const int lbase = lane & 24;
        #pragma unroll
        for (int s = 0; s < 8; s++) {
            float t0 = __shfl_sync(0xffffffffu, ts0, lbase + s);
            float t1 = __shfl_sync(0xffffffffu, ts1, lbase + s);
            float t2 = __shfl_sync(0xffffffffu, ts2, lbase + s);
            w1 += m1rv[s] * t0;
            w2 += m1rv[s] * t1;
            w3 += m1rv[s] * t2;
        }

        const int o = oc * 16 + ue;
        const float bias = __ldg(cb + o);
        const float inv_s8 = 0.3535533905932738f;  // 1/sqrt(8)
        const float wa7 = w1 * inv_s8 + w3;
        const float wa6 = w2 * inv_s8;
        const float gb  = bias * sG[re];

        float a[8];
        #pragma unroll
        for (int cc = 0; cc < 8; cc++) {
            float4 m1a = *(const float4*)(sM1 + cc * 8);
            float4 m1b = *(const float4*)(sM1 + cc * 8 + 4);
            float4 m2a = *(const float4*)(sM2 + cc * 8);
            float4 m2b = *(const float4*)(sM2 + cc * 8 + 4);
            float v = (cc < 4 ? ((const float*)&z0a)[cc] : ((const float*)&z0b)[cc - 4]);
            v += dot4(m1a, z1a) + dot4(m1b, z1b);
            v += dot4(m2a, z2a) + dot4(m2b, z2b);
            v += wa7 * sA7[cc] + wa6 * sA6[cc] + gb * sG[cc];
            a[cc] = v;
        }

        float* outp = out + (bb * 64 + o) * (size_t)65536
                          + (size_t)(y0 + re) * 256 + x0 + Be * 8;
        *(float4*)outp       = make_float4(a[0], a[1], a[2], a[3]);
        *(float4*)(outp + 4) = make_float4(a[4], a[5], a[6], a[7]);
    };

    // ---- software pipeline: 1 barrier per oc ----
    gemm_store(0, sm + ZB0_F);
    __syncthreads();
    #pragma unroll
    for (int oc = 0; oc < 4; oc++) {
        if (oc < 3) gemm_store(oc + 1, sm + ((oc & 1) ? ZB0_F : ZB1_F));
        epilogue(oc, sm + ((oc & 1) ? ZB1_F : ZB0_F));
        __syncthreads();
    }
}

extern "C" void kernel_launch(void* const* d_in, const int* in_sizes, int n_in,
                              void* d_out, int out_size) {
    const float* x  = (const float*)d_in[0];
    const float* cw = (const float*)d_in[1];
    const float* cb = (const float*)d_in[2];
    float* out = (float*)d_out;
    (void)in_sizes; (void)n_in; (void)out_size;

    cudaFuncSetAttribute(dctconv_mma, cudaFuncAttributeMaxDynamicSharedMemorySize,
                         SM_FLOATS * (int)sizeof(float));

    init_consts_kernel<<<1, 192>>>();
    dim3 grid(8, 32, 8);   // (W/32, H/8, bsz)
    dctconv_mma<<<grid, 512, SM_FLOATS * sizeof(float)>>>(x, cw, cb, out);
}

// round 12
// speedup vs baseline: 1.1956x; 1.0519x over previous
#include <cuda_runtime.h>
#include <math.h>

// x (8,64,256,256) fp32, conv_w (64,64,3), conv_b (64) -> out (8,64,256,256) fp32
// out_o = z0 + z1 M1^T + z2 M2^T
//       + (M1 (z1 a0)) a7^T + (M1 (z2 a0)) a6^T + (M1 (z2 a1)) a7^T + b_o g g^T
// z[px][j=o*3+kk] = sum_ch X[px][ch] W[j][ch], via mma.sync tf32 m16n8k8.
// R12: R9/R10 with Zb stride fixed 134 -> 132 (float4 alignment; 134%4==2 caused
//      the misaligned-address trap). 128-px CTA, 256 thr, ~89 KB smem, 2 CTAs/SM.

typedef unsigned int u32;

__device__ float c_all[160];  // [0:64) M1, [64:128) M2, [128:136) a1, [136:144) a6, [144:152) a7, [152:160) g

__device__ double Dkn(int k, int n) {
    const double PI = 3.14159265358979323846;
    double v = 0.5 * cos(PI * (2.0 * n + 1.0) * (double)k / 16.0);
    if (k == 0) v *= 0.7071067811865476;
    return v;
}

__global__ void init_consts_kernel() {
    int t = threadIdx.x;
    if (t >= 160) return;
    double r = 0.0;
    if (t < 64) {
        int p = t >> 3, q = t & 7;
        for (int n = 0; n < 7; n++) r += Dkn(n, p) * Dkn(n + 1, q);
    } else if (t < 128) {
        int s = t - 64; int p = s >> 3, q = s & 7;
        for (int n = 0; n < 6; n++) r += Dkn(n, p) * Dkn(n + 2, q);
    } else if (t < 136) r = Dkn(1, t - 128);
    else if (t < 144)   r = Dkn(6, t - 136);
    else if (t < 152)   r = Dkn(7, t - 144);
    else {
        int n = t - 152;
        for (int k = 0; k < 8; k++) r += Dkn(k, n);
    }
    c_all[t] = (float)r;
}

// smem float offsets (total 22,208 floats = 88,832 B -> 2 CTAs/SM)
#define XS_F 0                 // Xs[64 ch][132] (px 0..127); dead after af-load -> Zb1 overlay
#define ZB1_F 0                // Zb1[48][132] = 6336 <= 8448
#define WD_F 8448              // Wd[2][64 ch][56]  (48 j + pad), 7168
#define ZB0_F 15616            // Zb0[48][132] = 6336
#define SC_F 22048             // consts [160]
#define SM_FLOATS 22208

#define ZSTR 132               // Zb row stride: == 0 mod 4 (float4-aligned), == 4 mod 32

__device__ __forceinline__ float tf32r(float f) {
    u32 r;
    asm("cvt.rna.tf32.f32 %0, %1;" : "=r"(r) : "f"(f));
    return __uint_as_float(r);
}

__device__ __forceinline__ void mma_tf32(float* d, const float* a, const float* b) {
    asm volatile(
        "mma.sync.aligned.m16n8k8.row.col.f32.tf32.tf32.f32 "
        "{%0,%1,%2,%3}, {%4,%5,%6,%7}, {%8,%9}, {%0,%1,%2,%3};"
        : "+f"(d[0]), "+f"(d[1]), "+f"(d[2]), "+f"(d[3])
        : "r"(__float_as_uint(a[0])), "r"(__float_as_uint(a[1])),
          "r"(__float_as_uint(a[2])), "r"(__float_as_uint(a[3])),
          "r"(__float_as_uint(b[0])), "r"(__float_as_uint(b[1])));
}

__device__ __forceinline__ float dot4(float4 a, float4 b) {
    return a.x * b.x + a.y * b.y + a.z * b.z + a.w * b.w;
}
__device__ __forceinline__ float hsum4(float4 a) { return a.x + a.y + a.z + a.w; }

__global__ void __launch_bounds__(256, 2) dctconv_mma(
    const float* __restrict__ x,
    const float* __restrict__ cw,
    const float* __restrict__ cb,
    float* __restrict__ out)
{
    extern __shared__ float sm[];
    float* Xs = sm + XS_F;
    float* sC = sm + SC_F;

    const int tid = threadIdx.x;
    const int wid = tid >> 5;
    const int lane = tid & 31;
    const int g = lane >> 2;     // 0..7
    const int c = lane & 3;      // 0..3
    const int y0 = blockIdx.y * 8;
    const int x0 = blockIdx.x * 16;
    const size_t bb = blockIdx.z;

    if (tid < 160) sC[tid] = c_all[tid];

    // ---- W chunk loader: Wd[buf][i*56 + u*3+kk] <- cw[oc*3072 + v], tf32 ----
    auto loadW = [&](int oc, int buf) {
        float* Wd = sm + WD_F + buf * 3584;
        const float* src = cw + oc * 3072;
        #pragma unroll
        for (int k = 0; k < 12; k++) {
            int v = tid + 256 * k;           // v = u*192 + i*3 + kk
            int u = v / 192, r2 = v - u * 192;
            int i = r2 / 3, kk = r2 - i * 3;
            Wd[i * 56 + u * 3 + kk] = tf32r(src[v]);
        }
    };

    // ---- stage X: Xs[ch][px], px = B*64 + r*8 + cc (block-major), tf32 ----
    const float* xb = x + bb * (size_t)(64 * 65536);
    #pragma unroll
    for (int k = 0; k < 8; k++) {
        int v = tid + 256 * k;               // 2048 float4
        int i = v >> 5, q = v & 31;
        int B = q >> 4, r = (q >> 1) & 7, c4 = (q & 1) * 4;
        float4 t = *(const float4*)(xb + (size_t)i * 65536 + (y0 + r) * 256 + x0 + B * 8 + c4);
        t.x = tf32r(t.x); t.y = tf32r(t.y); t.z = tf32r(t.z); t.w = tf32r(t.w);
        *(float4*)(Xs + i * ZSTR + B * 64 + r * 8 + c4) = t;
    }
    loadW(0, 0);
    loadW(1, 1);
    __syncthreads();

    const float* sM1 = sC;
    const float* sM2 = sC + 64;
    const float* sA1 = sC + 128;
    const float* sA6 = sC + 136;
    const float* sA7 = sC + 144;
    const float* sG  = sC + 152;

    // GEMM mapping: 8 warps = 4 m-groups (32 px) x 2 n-groups (24 j)
    const int mg = wid >> 1;
    const int ng = wid & 1;
    const int px0 = mg * 32;
    const int jb = ng * 24;
    const u32 sxor = (mg & 1) << 2;          // px bit5 swizzle for this warp

    // ---- hoist oc-invariant a-fragments: af[k8][t][4] = 64 regs ----
    float af[8][2][4];
    #pragma unroll
    for (int k8 = 0; k8 < 8; k8++) {
        const float* Xc0 = Xs + (k8 * 8 + c) * ZSTR + px0 + g;
        const float* Xc4 = Xc0 + 4 * ZSTR;
        #pragma unroll
        for (int t = 0; t < 2; t++) {
            af[k8][t][0] = Xc0[16 * t];
            af[k8][t][1] = Xc0[16 * t + 8];
            af[k8][t][2] = Xc4[16 * t];
            af[k8][t][3] = Xc4[16 * t + 8];
        }
    }

    // GEMM for oc-group: reads Wd[buf], writes Zw (stride ZSTR, swizzled px)
    auto gemm_store = [&](int buf, float* Zw) {
        const float* Wd = sm + WD_F + buf * 3584;
        float acc[2][3][4];
        #pragma unroll
        for (int t = 0; t < 2; t++)
            #pragma unroll
            for (int nt = 0; nt < 3; nt++)
                #pragma unroll
                for (int e = 0; e < 4; e++) acc[t][nt][e] = 0.f;

        #pragma unroll
        for (int k8 = 0; k8 < 8; k8++) {
            const float* Wc0 = Wd + (k8 * 8 + c) * 56 + jb + g;
            const float* Wc4 = Wc0 + 4 * 56;
            float b[3][2];
            #pragma unroll
            for (int nt = 0; nt < 3; nt++) {
                b[nt][0] = Wc0[8 * nt];
                b[nt][1] = Wc4[8 * nt];
            }
            #pragma unroll
            for (int t = 0; t < 2; t++)
                #pragma unroll
                for (int nt = 0; nt < 3; nt++)
                    mma_tf32(acc[t][nt], af[k8][t], b[nt]);
        }
        #pragma unroll
        for (int t = 0; t < 2; t++)
            #pragma unroll
            for (int nt = 0; nt < 3; nt++) {
                int jl = jb + nt * 8 + 2 * c;
                int pxs = (px0 + 16 * t + g) ^ sxor;
                Zw[jl * ZSTR + pxs]             = acc[t][nt][0];
                Zw[(jl + 1) * ZSTR + pxs]       = acc[t][nt][1];
                Zw[jl * ZSTR + (pxs ^ 8)]       = acc[t][nt][2];
                Zw[(jl + 1) * ZSTR + (pxs ^ 8)] = acc[t][nt][3];
            }
    };

    // epilogue unit mapping: u = tid>>4 (2 per warp), B = (tid>>3)&1, r = tid&7
    const int ue = tid >> 4;
    const int Be = (lane >> 3) & 1;
    const int re = lane & 7;
    const int ro = re * 8;

    auto epilogue = [&](int oc, const float* Zr) {
        const float* zp = Zr + (ue * 3) * ZSTR + Be * 64;
        const int o0 = ro + ((re & 4) ? 4 : 0);
        const int o1 = ro + ((re & 4) ? 0 : 4);
        float4 z0a = *(const float4*)(zp + o0),             z0b = *(const float4*)(zp + o1);
        float4 z1a = *(const float4*)(zp + ZSTR + o0),      z1b = *(const float4*)(zp + ZSTR + o1);
        float4 z2a = *(const float4*)(zp + 2 * ZSTR + o0),  z2b = *(const float4*)(zp + 2 * ZSTR + o1);

        float4 a1a = *(const float4*)sA1;
        float4 a1b = *(const float4*)(sA1 + 4);
        float ts0 = hsum4(z1a) + hsum4(z1b);
        float ts1 = hsum4(z2a) + hsum4(z2b);
        float ts2 = dot4(z2a, a1a) + dot4(z2b, a1b);

        float4 m1ra = *(const float4*)(sM1 + re * 8);
        float4 m1rb = *(const float4*)(sM1 + re * 8 + 4);
        float m1rv[8] = {m1ra.x, m1ra.y, m1ra.z, m1ra.w, m1rb.x, m1rb.y, m1rb.z, m1rb.w};

        float w1 = 0.f, w2 = 0.f, w3 = 0.f;
        const int lbase = lane & 24;            // lanes with same (u, B), r = 0..7
        #pragma unroll
        for (int s = 0; s < 8; s++) {
            float t0 = __shfl_sync(0xffffffffu, ts0, lbase + s);
            float t1 = __shfl_sync(0xffffffffu, ts1, lbase + s);
            float t2 = __shfl_sync(0xffffffffu, ts2, lbase + s);
            w1 += m1rv[s] * t0;
            w2 += m1rv[s] * t1;
            w3 += m1rv[s] * t2;
        }

        const int o = oc * 16 + ue;
        const float bias = __ldg(cb + o);
        const float inv_s8 = 0.3535533905932738f;  // 1/sqrt(8)
        const float wa7 = w1 * inv_s8 + w3;
        const float wa6 = w2 * inv_s8;
        const float gb  = bias * sG[re];

        float a[8];
        #pragma unroll
        for (int cc = 0; cc < 8; cc++) {
            float4 m1a = *(const float4*)(sM1 + cc * 8);
            float4 m1b = *(const float4*)(sM1 + cc * 8 + 4);
            float4 m2a = *(const float4*)(sM2 + cc * 8);
            float4 m2b = *(const float4*)(sM2 + cc * 8 + 4);
            float v = (cc < 4 ? ((const float*)&z0a)[cc] : ((const float*)&z0b)[cc - 4]);
            v += dot4(m1a, z1a) + dot4(m1b, z1b);
            v += dot4(m2a, z2a) + dot4(m2b, z2b);
            v += wa7 * sA7[cc] + wa6 * sA6[cc] + gb * sG[cc];
            a[cc] = v;
        }

        float* outp = out + (bb * 64 + o) * (size_t)65536
                          + (size_t)(y0 + re) * 256 + x0 + Be * 8;
        *(float4*)outp       = make_float4(a[0], a[1], a[2], a[3]);
        *(float4*)(outp + 4) = make_float4(a[4], a[5], a[6], a[7]);
    };

    // ---- software pipeline: W one iter ahead, gemm one iter ahead of epilogue ----
    gemm_store(0, sm + ZB0_F);
    __syncthreads();
    #pragma unroll
    for (int oc = 0; oc < 4; oc++) {
        if (oc < 2) loadW(oc + 2, oc & 1);
        if (oc < 3) gemm_store((oc + 1) & 1, sm + ((oc & 1) ? ZB0_F : ZB1_F));
        epilogue(oc, sm + ((oc & 1) ? ZB1_F : ZB0_F));
        __syncthreads();
    }
}

extern "C" void kernel_launch(void* const* d_in, const int* in_sizes, int n_in,
                              void* d_out, int out_size) {
    const float* x  = (const float*)d_in[0];
    const float* cw = (const float*)d_in[1];
    const float* cb = (const float*)d_in[2];
    float* out = (float*)d_out;
    (void)in_sizes; (void)n_in; (void)out_size;

    cudaFuncSetAttribute(dctconv_mma, cudaFuncAttributeMaxDynamicSharedMemorySize,
                         SM_FLOATS * (int)sizeof(float));

    init_consts_kernel<<<1, 192>>>();
    dim3 grid(16, 32, 8);   // (W/16, H/8, bsz)
    dctconv_mma<<<grid, 256, SM_FLOATS * sizeof(float)>>>(x, cw, cb, out);
}

// round 16
// speedup vs baseline: 1.4518x; 1.2143x over previous
#include <cuda_runtime.h>
#include <math.h>

// x (8,64,256,256) fp32, conv_w (64,64,3), conv_b (64) -> out (8,64,256,256) fp32
// out_o = z0 + z1 M1^T + z2 M2^T
//       + (M1 (z1 a0)) a7^T + (M1 (z2 a0)) a6^T + (M1 (z2 a1)) a7^T + b_o g g^T
// z[px][j=o*3+kk] = sum_ch X[px][ch] W[j][ch], via mma.sync tf32 m16n8k8.
// R13: uniform constants -> __constant__ (off the crossbar); Xs stride 136
//      (conflict-free af loads); stride-12 M1-row copy; W fragment layout
//      precomputed in an init kernel (no div/mod in loadW).

typedef unsigned int u32;

__device__ float c_all[160];   // [0:64) M1, [64:128) M2, [128:136) a1, [136:144) a6, [144:152) a7, [152:160) g
__device__ float w_pre[4 * 3584];  // per-oc fragment layout: [oc][i*56 + u*3 + kk], tf32-rounded
__constant__ float cM[160];    // same as c_all, for uniform-offset access

__device__ double Dkn(int k, int n) {
    const double PI = 3.14159265358979323846;
    double v = 0.5 * cos(PI * (2.0 * n + 1.0) * (double)k / 16.0);
    if (k == 0) v *= 0.7071067811865476;
    return v;
}

__global__ void init_consts_kernel() {
    int t = threadIdx.x;
    if (t >= 160) return;
    double r = 0.0;
    if (t < 64) {
        int p = t >> 3, q = t & 7;
        for (int n = 0; n < 7; n++) r += Dkn(n, p) * Dkn(n + 1, q);
    } else if (t < 128) {
        int s = t - 64; int p = s >> 3, q = s & 7;
        for (int n = 0; n < 6; n++) r += Dkn(n, p) * Dkn(n + 2, q);
    } else if (t < 136) r = Dkn(1, t - 128);
    else if (t < 144)   r = Dkn(6, t - 136);
    else if (t < 152)   r = Dkn(7, t - 144);
    else {
        int n = t - 152;
        for (int k = 0; k < 8; k++) r += Dkn(k, n);
    }
    c_all[t] = (float)r;
}

__device__ __forceinline__ float tf32r(float f) {
    u32 r;
    asm("cvt.rna.tf32.f32 %0, %1;" : "=r"(r) : "f"(f));
    return __uint_as_float(r);
}

__global__ void init_w_kernel(const float* __restrict__ cw) {
    int v = blockIdx.x * 256 + threadIdx.x;   // 0..12287 ; cw index = o*192 + i*3 + kk = v
    if (v >= 12288) return;
    int o = v / 192, rem = v - o * 192;
    int i = rem / 3, kk = rem - i * 3;
    int oc = o >> 4, u = o & 15;
    w_pre[oc * 3584 + i * 56 + u * 3 + kk] = tf32r(cw[v]);
}

// smem float offsets (total 22,464 floats = 89,856 B -> 2 CTAs/SM)
#define XS_F 0                 // Xs[64 ch][136]; dead after af-load -> ZB1 overlay (needs 8704)
#define ZB1_F 0                // Zb1[48][132] = 6336
#define WD_F 8704              // Wd[2][3584]
#define ZB0_F 15872            // Zb0[48][132] = 6336
#define SC_F 22208             // consts [160] (per-thread-indexed uses)
#define SC2_F 22368            // M1 rows, stride 12: [8][12] = 96
#define SM_FLOATS 22464

#define XSTR 136               // == 8 mod 32 -> af banks 8c+g, conflict-free
#define ZSTR 132               // == 0 mod 4 (float4), == 4 mod 32

__device__ __forceinline__ void mma_tf32(float* d, const float* a, const float* b) {
    asm volatile(
        "mma.sync.aligned.m16n8k8.row.col.f32.tf32.tf32.f32 "
        "{%0,%1,%2,%3}, {%4,%5,%6,%7}, {%8,%9}, {%0,%1,%2,%3};"
        : "+f"(d[0]), "+f"(d[1]), "+f"(d[2]), "+f"(d[3])
        : "r"(__float_as_uint(a[0])), "r"(__float_as_uint(a[1])),
          "r"(__float_as_uint(a[2])), "r"(__float_as_uint(a[3])),
          "r"(__float_as_uint(b[0])), "r"(__float_as_uint(b[1])));
}

__device__ __forceinline__ float dot4(float4 a, float4 b) {
    return a.x * b.x + a.y * b.y + a.z * b.z + a.w * b.w;
}
__device__ __forceinline__ float hsum4(float4 a) { return a.x + a.y + a.z + a.w; }

__global__ void __launch_bounds__(256, 2) dctconv_mma(
    const float* __restrict__ x,
    const float* __restrict__ cw,
    const float* __restrict__ cb,
    float* __restrict__ out)
{
    extern __shared__ float sm[];
    float* Xs  = sm + XS_F;
    float* sC  = sm + SC_F;
    float* sC2 = sm + SC2_F;

    const int tid = threadIdx.x;
    const int wid = tid >> 5;
    const int lane = tid & 31;
    const int g = lane >> 2;     // 0..7
    const int c = lane & 3;      // 0..3
    const int y0 = blockIdx.y * 8;
    const int x0 = blockIdx.x * 16;
    const size_t bb = blockIdx.z;

    if (tid < 160) sC[tid] = c_all[tid];
    if (tid < 64) sC2[(tid >> 3) * 12 + (tid & 7)] = c_all[tid];   // M1 rows, stride 12

    // ---- W chunk loader: plain coalesced copy from precomputed layout ----
    auto loadW = [&](int oc, int buf) {
        float* Wd = sm + WD_F + buf * 3584;
        const float* src = w_pre + oc * 3584;
        #pragma unroll
        for (int k = 0; k < 14; k++)
            Wd[tid + 256 * k] = src[tid + 256 * k];
    };

    // ---- stage X: Xs[ch][px], px = B*64 + r*8 + cc (block-major), tf32 ----
    const float* xb = x + bb * (size_t)(64 * 65536);
    #pragma unroll
    for (int k = 0; k < 8; k++) {
        int v = tid + 256 * k;               // 2048 float4
        int i = v >> 5, q = v & 31;
        int B = q >> 4, r = (q >> 1) & 7, c4 = (q & 1) * 4;
        float4 t = *(const float4*)(xb + (size_t)i * 65536 + (y0 + r) * 256 + x0 + B * 8 + c4);
        t.x = tf32r(t.x); t.y = tf32r(t.y); t.z = tf32r(t.z); t.w = tf32r(t.w);
        *(float4*)(Xs + i * XSTR + B * 64 + r * 8 + c4) = t;
    }
    loadW(0, 0);
    loadW(1, 1);
    __syncthreads();

    // GEMM mapping: 8 warps = 4 m-groups (32 px) x 2 n-groups (24 j)
    const int mg = wid >> 1;
    const int ng = wid & 1;
    const int px0 = mg * 32;
    const int jb = ng * 24;
    const u32 sxor = (mg & 1) << 2;          // px bit5 swizzle for this warp

    // ---- hoist oc-invariant a-fragments: af[k8][t][4] = 64 regs (conflict-free) ----
    float af[8][2][4];
    #pragma unroll
    for (int k8 = 0; k8 < 8; k8++) {
        const float* Xc0 = Xs + (k8 * 8 + c) * XSTR + px0 + g;
        const float* Xc4 = Xc0 + 4 * XSTR;
        #pragma unroll
        for (int t = 0; t < 2; t++) {
            af[k8][t][0] = Xc0[16 * t];
            af[k8][t][1] = Xc0[16 * t + 8];
            af[k8][t][2] = Xc4[16 * t];
            af[k8][t][3] = Xc4[16 * t + 8];
        }
    }

    // GEMM for oc-group: reads Wd[buf], writes Zw (stride ZSTR, swizzled px)
    auto gemm_store = [&](int buf, float* Zw) {
        const float* Wd = sm + WD_F + buf * 3584;
        float acc[2][3][4];
        #pragma unroll
        for (int t = 0; t < 2; t++)
            #pragma unroll
            for (int nt = 0; nt < 3; nt++)
                #pragma unroll
                for (int e = 0; e < 4; e++) acc[t][nt][e] = 0.f;

        #pragma unroll
        for (int k8 = 0; k8 < 8; k8++) {
            const float* Wc0 = Wd + (k8 * 8 + c) * 56 + jb + g;
            const float* Wc4 = Wc0 + 4 * 56;
            float b[3][2];
            #pragma unroll
            for (int nt = 0; nt < 3; nt++) {
                b[nt][0] = Wc0[8 * nt];
                b[nt][1] = Wc4[8 * nt];
            }
            #pragma unroll
            for (int t = 0; t < 2; t++)
                #pragma unroll
                for (int nt = 0; nt < 3; nt++)
                    mma_tf32(acc[t][nt], af[k8][t], b[nt]);
        }
        #pragma unroll
        for (int t = 0; t < 2; t++)
            #pragma unroll
            for (int nt = 0; nt < 3; nt++) {
                int jl = jb + nt * 8 + 2 * c;
                int pxs = (px0 + 16 * t + g) ^ sxor;
                Zw[jl * ZSTR + pxs]             = acc[t][nt][0];
                Zw[(jl + 1) * ZSTR + pxs]       = acc[t][nt][1];
                Zw[jl * ZSTR + (pxs ^ 8)]       = acc[t][nt][2];
                Zw[(jl + 1) * ZSTR + (pxs ^ 8)] = acc[t][nt][3];
            }
    };

    // epilogue unit mapping: u = tid>>4 (2 per warp), B = (tid>>3)&1, r = lane&7
    const int ue = tid >> 4;
    const int Be = (lane >> 3) & 1;
    const int re = lane & 7;
    const int ro = re * 8;

    auto epilogue = [&](int oc, const float* Zr) {
        const float* zp = Zr + (ue * 3) * ZSTR + Be * 64;
        const int o0 = ro + ((re & 4) ? 4 : 0);
        const int o1 = ro + ((re & 4) ? 0 : 4);
        float4 z0a = *(const float4*)(zp + o0),             z0b = *(const float4*)(zp + o1);
        float4 z1a = *(const float4*)(zp + ZSTR + o0),      z1b = *(const float4*)(zp + ZSTR + o1);
        float4 z2a = *(const float4*)(zp + 2 * ZSTR + o0),  z2b = *(const float4*)(zp + 2 * ZSTR + o1);

        // uniform constants from cmem (off the crossbar)
        float4 a1a = *(const float4*)(cM + 128);
        float4 a1b = *(const float4*)(cM + 132);
        float ts0 = hsum4(z1a) + hsum4(z1b);
        float ts1 = hsum4(z2a) + hsum4(z2b);
        float ts2 = dot4(z2a, a1a) + dot4(z2b, a1b);

        // per-thread-indexed M1 row from padded smem copy (stride 12, conflict-free)
        float4 m1ra = *(const float4*)(sC2 + re * 12);
        float4 m1rb = *(const float4*)(sC2 + re * 12 + 4);
        float m1rv[8] = {m1ra.x, m1ra.y, m1ra.z, m1ra.w, m1rb.x, m1rb.y, m1rb.z, m1rb.w};

        float w1 = 0.f, w2 = 0.f, w3 = 0.f;
        const int lbase = lane & 24;            // lanes with same (u, B), r = 0..7
        #pragma unroll
        for (int s = 0; s < 8; s++) {
            float t0 = __shfl_sync(0xffffffffu, ts0, lbase + s);
            float t1 = __shfl_sync(0xffffffffu, ts1, lbase + s);
            float t2 = __shfl_sync(0xffffffffu, ts2, lbase + s);
            w1 += m1rv[s] * t0;
            w2 += m1rv[s] * t1;
            w3 += m1rv[s] * t2;
        }

        const int o = oc * 16 + ue;
        const float bias = __ldg(cb + o);
        const float inv_s8 = 0.3535533905932738f;  // 1/sqrt(8)
        const float wa7 = w1 * inv_s8 + w3;
        const float wa6 = w2 * inv_s8;
        const float gb  = bias * sC[152 + re];      // g[re], per-thread index -> smem

        float a[8];
        #pragma unroll
        for (int cc = 0; cc < 8; cc++) {
            float4 m1a = *(const float4*)(cM + cc * 8);
            float4 m1b = *(const float4*)(cM + cc * 8 + 4);
            float4 m2a = *(const float4*)(cM + 64 + cc * 8);
            float4 m2b = *(const float4*)(cM + 64 + cc * 8 + 4);
            float v = (cc < 4 ? ((const float*)&z0a)[cc] : ((const float*)&z0b)[cc - 4]);
            v += dot4(m1a, z1a) + dot4(m1b, z1b);
            v += dot4(m2a, z2a) + dot4(m2b, z2b);
            v += wa7 * cM[144 + cc] + wa6 * cM[136 + cc] + gb * cM[152 + cc];
            a[cc] = v;
        }

        float* outp = out + (bb * 64 + o) * (size_t)65536
                          + (size_t)(y0 + re) * 256 + x0 + Be * 8;
        *(float4*)outp       = make_float4(a[0], a[1], a[2], a[3]);
        *(float4*)(outp + 4) = make_float4(a[4], a[5], a[6], a[7]);
    };

    // ---- software pipeline: W one iter ahead, gemm one iter ahead of epilogue ----
    gemm_store(0, sm + ZB0_F);
    __syncthreads();
    #pragma unroll
    for (int oc = 0; oc < 4; oc++) {
        if (oc < 2) loadW(oc + 2, oc & 1);
        if (oc < 3) gemm_store((oc + 1) & 1, sm + ((oc & 1) ? ZB0_F : ZB1_F));
        epilogue(oc, sm + ((oc & 1) ? ZB1_F : ZB0_F));
        __syncthreads();
    }
}

extern "C" void kernel_launch(void* const* d_in, const int* in_sizes, int n_in,
                              void* d_out, int out_size) {
    const float* x  = (const float*)d_in[0];
    const float* cw = (const float*)d_in[1];
    const float* cb = (const float*)d_in[2];
    float* out = (float*)d_out;
    (void)in_sizes; (void)n_in; (void)out_size;

    cudaFuncSetAttribute(dctconv_mma, cudaFuncAttributeMaxDynamicSharedMemorySize,
                         SM_FLOATS * (int)sizeof(float));

    init_consts_kernel<<<1, 192>>>();
    init_w_kernel<<<48, 256>>>(cw);

    // mirror c_all into __constant__ cM (async D2D, graph-capturable)
    void* c_all_addr = nullptr;
    cudaGetSymbolAddress(&c_all_addr, c_all);
    cudaMemcpyToSymbolAsync(cM, c_all_addr, 160 * sizeof(float), 0,
                            cudaMemcpyDeviceToDevice, 0);

    dim3 grid(16, 32, 8);   // (W/16, H/8, bsz)
    dctconv_mma<<<grid, 256, SM_FLOATS * sizeof(float)>>>(x, cw, cb, out);
}

// round 17
// speedup vs baseline: 1.5910x; 1.0959x over previous
#include <cuda_runtime.h>
#include <math.h>

// x (8,64,256,256) fp32, conv_w (64,64,3), conv_b (64) -> out (8,64,256,256) fp32
// out_o = z0 + z1 M1^T + z2 M2^T
//       + (M1 (z1 a0)) a7^T + (M1 (z2 a0)) a6^T + (M1 (z2 a1)) a7^T + b_o g g^T
// z[px][j=o*3+kk] = sum_ch X[px][ch] W[j][ch], via mma.sync tf32 m16n8k8.
// R17: DCT-derived constants computed at COMPILE TIME into __constant__ memory
//      (kills the 19us init_consts launch + memcpyToSymbol graph nodes).

typedef unsigned int u32;

// ---- compile-time constant table ----
// cos(pi*m/16) for m = 0..8
constexpr double kCos16[9] = {
    1.0,
    0.98078528040323044913,
    0.92387953251128675613,
    0.83146961230254523708,
    0.70710678118654752440,
    0.55557023301960222474,
    0.38268343236508977173,
    0.19509032201612826785,
    0.0
};

constexpr double cpi16(int m) {
    m %= 32; if (m < 0) m += 32;
    if (m <= 8)  return kCos16[m];
    if (m <= 16) return -kCos16[16 - m];
    if (m <= 24) return -kCos16[m - 16];
    return kCos16[32 - m];
}
constexpr double Dc(int k, int n) {
    double v = 0.5 * cpi16((2 * n + 1) * k);        // sqrt(2/8) = 0.5
    return (k == 0) ? v * 0.70710678118654752440 : v;
}

struct __align__(16) CTab { float v[160]; };  // [0:64) M1, [64:128) M2, [128:136) a1, [136:144) a6, [144:152) a7, [152:160) g

constexpr CTab make_ctab() {
    CTab t{};
    for (int p = 0; p < 8; p++)
        for (int q = 0; q < 8; q++) {
            double m1 = 0.0, m2 = 0.0;
            for (int n = 0; n < 7; n++) m1 += Dc(n, p) * Dc(n + 1, q);
            for (int n = 0; n < 6; n++) m2 += Dc(n, p) * Dc(n + 2, q);
            t.v[p * 8 + q]      = (float)m1;
            t.v[64 + p * 8 + q] = (float)m2;
        }
    for (int n = 0; n < 8; n++) {
        t.v[128 + n] = (float)Dc(1, n);
        t.v[136 + n] = (float)Dc(6, n);
        t.v[144 + n] = (float)Dc(7, n);
        double gg = 0.0;
        for (int k = 0; k < 8; k++) gg += Dc(k, n);
        t.v[152 + n] = (float)gg;
    }
    return t;
}

__constant__ CTab cTab = make_ctab();

__device__ float w_pre[4 * 3584];  // per-oc fragment layout: [oc][i*56 + u*3 + kk], tf32-rounded

__device__ __forceinline__ float tf32r(float f) {
    u32 r;
    asm("cvt.rna.tf32.f32 %0, %1;" : "=r"(r) : "f"(f));
    return __uint_as_float(r);
}

__global__ void init_w_kernel(const float* __restrict__ cw) {
    int v = blockIdx.x * 256 + threadIdx.x;   // 0..12287 ; cw index = o*192 + i*3 + kk = v
    if (v >= 12288) return;
    int o = v / 192, rem = v - o * 192;
    int i = rem / 3, kk = rem - i * 3;
    int oc = o >> 4, u = o & 15;
    w_pre[oc * 3584 + i * 56 + u * 3 + kk] = tf32r(cw[v]);
}

// smem float offsets (total 22,464 floats = 89,856 B -> 2 CTAs/SM)
#define XS_F 0                 // Xs[64 ch][136]; dead after af-load -> ZB1 overlay (needs 8704)
#define ZB1_F 0                // Zb1[48][132] = 6336
#define WD_F 8704              // Wd[2][3584]
#define ZB0_F 15872            // Zb0[48][132] = 6336
#define SC_F 22208             // consts [160] (per-thread-indexed uses)
#define SC2_F 22368            // M1 rows, stride 12: [8][12] = 96
#define SM_FLOATS 22464

#define XSTR 136               // == 8 mod 32 -> af banks 8c+g, conflict-free
#define ZSTR 132               // == 0 mod 4 (float4), == 4 mod 32

__device__ __forceinline__ void mma_tf32(float* d, const float* a, const float* b) {
    asm volatile(
        "mma.sync.aligned.m16n8k8.row.col.f32.tf32.tf32.f32 "
        "{%0,%1,%2,%3}, {%4,%5,%6,%7}, {%8,%9}, {%0,%1,%2,%3};"
        : "+f"(d[0]), "+f"(d[1]), "+f"(d[2]), "+f"(d[3])
        : "r"(__float_as_uint(a[0])), "r"(__float_as_uint(a[1])),
          "r"(__float_as_uint(a[2])), "r"(__float_as_uint(a[3])),
          "r"(__float_as_uint(b[0])), "r"(__float_as_uint(b[1])));
}

__device__ __forceinline__ float dot4(float4 a, float4 b) {
    return a.x * b.x + a.y * b.y + a.z * b.z + a.w * b.w;
}
__device__ __forceinline__ float hsum4(float4 a) { return a.x + a.y + a.z + a.w; }

__global__ void __launch_bounds__(256, 2) dctconv_mma(
    const float* __restrict__ x,
    const float* __restrict__ cw,
    const float* __restrict__ cb,
    float* __restrict__ out)
{
    extern __shared__ float sm[];
    float* Xs  = sm + XS_F;
    float* sC  = sm + SC_F;
    float* sC2 = sm + SC2_F;

    const int tid = threadIdx.x;
    const int wid = tid >> 5;
    const int lane = tid & 31;
    const int g = lane >> 2;     // 0..7
    const int c = lane & 3;      // 0..3
    const int y0 = blockIdx.y * 8;
    const int x0 = blockIdx.x * 16;
    const size_t bb = blockIdx.z;

    const float* cM = cTab.v;
    if (tid < 160) sC[tid] = cM[tid];
    if (tid < 64) sC2[(tid >> 3) * 12 + (tid & 7)] = cM[tid];   // M1 rows, stride 12

    // ---- W chunk loader: plain coalesced copy from precomputed layout ----
    auto loadW = [&](int oc, int buf) {
        float* Wd = sm + WD_F + buf * 3584;
        const float* src = w_pre + oc * 3584;
        #pragma unroll
        for (int k = 0; k < 14; k++)
            Wd[tid + 256 * k] = src[tid + 256 * k];
    };

    // ---- stage X: Xs[ch][px], px = B*64 + r*8 + cc (block-major), tf32 ----
    const float* xb = x + bb * (size_t)(64 * 65536);
    #pragma unroll
    for (int k = 0; k < 8; k++) {
        int v = tid + 256 * k;               // 2048 float4
        int i = v >> 5, q = v & 31;
        int B = q >> 4, r = (q >> 1) & 7, c4 = (q & 1) * 4;
        float4 t = *(const float4*)(xb + (size_t)i * 65536 + (y0 + r) * 256 + x0 + B * 8 + c4);
        t.x = tf32r(t.x); t.y = tf32r(t.y); t.z = tf32r(t.z); t.w = tf32r(t.w);
        *(float4*)(Xs + i * XSTR + B * 64 + r * 8 + c4) = t;
    }
    loadW(0, 0);
    loadW(1, 1);
    __syncthreads();

    // GEMM mapping: 8 warps = 4 m-groups (32 px) x 2 n-groups (24 j)
    const int mg = wid >> 1;
    const int ng = wid & 1;
    const int px0 = mg * 32;
    const int jb = ng * 24;
    const u32 sxor = (mg & 1) << 2;          // px bit5 swizzle for this warp

    // ---- hoist oc-invariant a-fragments: af[k8][t][4] = 64 regs (conflict-free) ----
    float af[8][2][4];
    #pragma unroll
    for (int k8 = 0; k8 < 8; k8++) {
        const float* Xc0 = Xs + (k8 * 8 + c) * XSTR + px0 + g;
        const float* Xc4 = Xc0 + 4 * XSTR;
        #pragma unroll
        for (int t = 0; t < 2; t++) {
            af[k8][t][0] = Xc0[16 * t];
            af[k8][t][1] = Xc0[16 * t + 8];
            af[k8][t][2] = Xc4[16 * t];
            af[k8][t][3] = Xc4[16 * t + 8];
        }
    }

    // GEMM for oc-group: reads Wd[buf], writes Zw (stride ZSTR, swizzled px)
    auto gemm_store = [&](int buf, float* Zw) {
        const float* Wd = sm + WD_F + buf * 3584;
        float acc[2][3][4];
        #pragma unroll
        for (int t = 0; t < 2; t++)
            #pragma unroll
            for (int nt = 0; nt < 3; nt++)
                #pragma unroll
                for (int e = 0; e < 4; e++) acc[t][nt][e] = 0.f;

        #pragma unroll
        for (int k8 = 0; k8 < 8; k8++) {
            const float* Wc0 = Wd + (k8 * 8 + c) * 56 + jb + g;
            const float* Wc4 = Wc0 + 4 * 56;
            float b[3][2];
            #pragma unroll
            for (int nt = 0; nt < 3; nt++) {
                b[nt][0] = Wc0[8 * nt];
                b[nt][1] = Wc4[8 * nt];
            }
            #pragma unroll
            for (int t = 0; t < 2; t++)
                #pragma unroll
                for (int nt = 0; nt < 3; nt++)
                    mma_tf32(acc[t][nt], af[k8][t], b[nt]);
        }
        #pragma unroll
        for (int t = 0; t < 2; t++)
            #pragma unroll
            for (int nt = 0; nt < 3; nt++) {
                int jl = jb + nt * 8 + 2 * c;
                int pxs = (px0 + 16 * t + g) ^ sxor;
                Zw[jl * ZSTR + pxs]             = acc[t][nt][0];
                Zw[(jl + 1) * ZSTR + pxs]       = acc[t][nt][1];
                Zw[jl * ZSTR + (pxs ^ 8)]       = acc[t][nt][2];
                Zw[(jl + 1) * ZSTR + (pxs ^ 8)] = acc[t][nt][3];
            }
    };

    // epilogue unit mapping: u = tid>>4 (2 per warp), B = (tid>>3)&1, r = lane&7
    const int ue = tid >> 4;
    const int Be = (lane >> 3) & 1;
    const int re = lane & 7;
    const int ro = re * 8;

    auto epilogue = [&](int oc, const float* Zr) {
        const float* zp = Zr + (ue * 3) * ZSTR + Be * 64;
        const int o0 = ro + ((re & 4) ? 4 : 0);
        const int o1 = ro + ((re & 4) ? 0 : 4);
        float4 z0a = *(const float4*)(zp + o0),             z0b = *(const float4*)(zp + o1);
        float4 z1a = *(const float4*)(zp + ZSTR + o0),      z1b = *(const float4*)(zp + ZSTR + o1);
        float4 z2a = *(const float4*)(zp + 2 * ZSTR + o0),  z2b = *(const float4*)(zp + 2 * ZSTR + o1);

        // uniform constants from cmem (off the crossbar)
        float4 a1a = *(const float4*)(cM + 128);
        float4 a1b = *(const float4*)(cM + 132);
        float ts0 = hsum4(z1a) + hsum4(z1b);
        float ts1 = hsum4(z2a) + hsum4(z2b);
        float ts2 = dot4(z2a, a1a) + dot4(z2b, a1b);

        // per-thread-indexed M1 row from padded smem copy (stride 12, conflict-free)
        float4 m1ra = *(const float4*)(sC2 + re * 12);
        float4 m1rb = *(const float4*)(sC2 + re * 12 + 4);
        float m1rv[8] = {m1ra.x, m1ra.y, m1ra.z, m1ra.w, m1rb.x, m1rb.y, m1rb.z, m1rb.w};

        float w1 = 0.f, w2 = 0.f, w3 = 0.f;
        const int lbase = lane & 24;            // lanes with same (u, B), r = 0..7
        #pragma unroll
        for (int s = 0; s < 8; s++) {
            float t0 = __shfl_sync(0xffffffffu, ts0, lbase + s);
            float t1 = __shfl_sync(0xffffffffu, ts1, lbase + s);
            float t2 = __shfl_sync(0xffffffffu, ts2, lbase + s);
            w1 += m1rv[s] * t0;
            w2 += m1rv[s] * t1;
            w3 += m1rv[s] * t2;
        }

        const int o = oc * 16 + ue;
        const float bias = __ldg(cb + o);
        const float inv_s8 = 0.3535533905932738f;  // 1/sqrt(8)
        const float wa7 = w1 * inv_s8 + w3;
        const float wa6 = w2 * inv_s8;
        const float gb  = bias * sC[152 + re];      // g[re], per-thread index -> smem

        float a[8];
        #pragma unroll
        for (int cc = 0; cc < 8; cc++) {
            float4 m1a = *(const float4*)(cM + cc * 8);
            float4 m1b = *(const float4*)(cM + cc * 8 + 4);
            float4 m2a = *(const float4*)(cM + 64 + cc * 8);
            float4 m2b = *(const float4*)(cM + 64 + cc * 8 + 4);
            float v = (cc < 4 ? ((const float*)&z0a)[cc] : ((const float*)&z0b)[cc - 4]);
            v += dot4(m1a, z1a) + dot4(m1b, z1b);
            v += dot4(m2a, z2a) + dot4(m2b, z2b);
            v += wa7 * cM[144 + cc] + wa6 * cM[136 + cc] + gb * cM[152 + cc];
            a[cc] = v;
        }

        float* outp = out + (bb * 64 + o) * (size_t)65536
                          + (size_t)(y0 + re) * 256 + x0 + Be * 8;
        *(float4*)outp       = make_float4(a[0], a[1], a[2], a[3]);
        *(float4*)(outp + 4) = make_float4(a[4], a[5], a[6], a[7]);
    };

    // ---- software pipeline: W one iter ahead, gemm one iter ahead of epilogue ----
    gemm_store(0, sm + ZB0_F);
    __syncthreads();
    #pragma unroll
    for (int oc = 0; oc < 4; oc++) {
        if (oc < 2) loadW(oc + 2, oc & 1);
        if (oc < 3) gemm_store((oc + 1) & 1, sm + ((oc & 1) ? ZB0_F : ZB1_F));
        epilogue(oc, sm + ((oc & 1) ? ZB1_F : ZB0_F));
        __syncthreads();
    }
}

extern "C" void kernel_launch(void* const* d_in, const int* in_sizes, int n_in,
                              void* d_out, int out_size) {
    const float* x  = (const float*)d_in[0];
    const float* cw = (const float*)d_in[1];
    const float* cb = (const float*)d_in[2];
    float* out = (float*)d_out;
    (void)in_sizes; (void)n_in; (void)out_size;

    cudaFuncSetAttribute(dctconv_mma, cudaFuncAttributeMaxDynamicSharedMemorySize,
                         SM_FLOATS * (int)sizeof(float));

    init_w_kernel<<<48, 256>>>(cw);

    dim3 grid(16, 32, 8);   // (W/16, H/8, bsz)
    dctconv_mma<<<grid, 256, SM_FLOATS * sizeof(float)>>>(x, cw, cb, out);
}